// round 15
// baseline (speedup 1.0000x reference)
#include <cuda_runtime.h>
#include <math.h>
#include <stdint.h>

#define Bn 2
#define Nn 2048
#define Qn 256
#define NITERS 15
#define KC 32   // smem staging chunk (load batching only)

// Scratch (device globals)
__device__ __align__(16) float g_h [Bn * Nn * Qn];
__device__ __align__(16) float g_h2[Bn * Nn * Qn];
__device__ __align__(16) float g_C [Bn * Nn * Qn];
__device__ float g_ne [Bn * Nn];
__device__ float g_ni [Bn * Nn];
__device__ float g_ne1[Bn * Nn];
__device__ float g_ni1[Bn * Nn];

// ---------------------------------------------------------------------------
// Column sums: serial ascending n, rn ops, separate mul/add (R8 verbatim)
// ---------------------------------------------------------------------------
template <bool ACT>
__global__ void colsum_kernel(const float* __restrict__ adj,
                              const float* __restrict__ act,
                              float* __restrict__ ne, float* __restrict__ ni) {
    int b = blockIdx.y;
    int m = blockIdx.x * 256 + threadIdx.x;
    const float* A = adj + (size_t)b * Nn * Nn + m;
    float se = 0.f, si = 0.f;
    for (int n = 0; n < Nn; n++) {
        float v = A[(size_t)n * Nn];
        float e = (v > 0.5f) ? v : 0.f;
        float w = __fsub_rn(1.0f, v);
        float ii = (w > 0.5f) ? w : 0.f;
        if (ACT) {
            float a = act[b * Nn + n];
            e = __fmul_rn(e, a);
            ii = __fmul_rn(ii, a);
        }
        se = __fadd_rn(se, e);
        si = __fadd_rn(si, ii);
    }
    ne[b * Nn + m] = fmaxf(se, 1.f);
    ni[b * Nn + m] = fmaxf(si, 1.f);
}

// ---------------------------------------------------------------------------
// GEMM: per-element strict serial ascending __fmaf_rn chain (R8 verbatim)
// ---------------------------------------------------------------------------
template <int MODE, bool ACT>
__global__ void __launch_bounds__(256)
gemm_serial(const float* __restrict__ adj, const float* __restrict__ act,
            const float* __restrict__ hin, float* __restrict__ Cout) {
    __shared__ float s_a[KC][32];
    __shared__ __align__(16) float s_h[KC][256];

    int b = blockIdx.y;
    int m0 = blockIdx.x * 32;
    int tid = threadIdx.x, lane = tid & 31, tm = tid >> 5;

    const float* Ab = adj + (size_t)b * Nn * Nn;
    const float4* Hv = (const float4*)(hin + (size_t)b * Nn * Qn);
    const float* av = ACT ? (act + b * Nn) : nullptr;

    float acc[4][8];
#pragma unroll
    for (int i = 0; i < 4; i++)
#pragma unroll
        for (int j = 0; j < 8; j++) acc[i][j] = 0.f;

    for (int k0 = 0; k0 < Nn; k0 += KC) {
#pragma unroll
        for (int i = 0; i < KC * 32 / 256; i++) {
            int idx = tid + i * 256;
            int kk = idx >> 5, mm = idx & 31;
            float v = Ab[(size_t)(k0 + kk) * Nn + m0 + mm];
            float t;
            if (MODE == 0) t = (v > 0.5f) ? v : 0.f;
            else { float w = __fsub_rn(1.f, v); t = (w > 0.5f) ? w : 0.f; }
            if (ACT) t = __fmul_rn(t, av[k0 + kk]);
            s_a[kk][mm] = t;
        }
#pragma unroll
        for (int i = 0; i < KC * 64 / 256; i++) {
            int idx = tid + i * 256;
            int kk = idx >> 6, c4 = idx & 63;
            ((float4*)s_h[kk])[c4] = Hv[(size_t)(k0 + kk) * 64 + c4];
        }
        __syncthreads();
#pragma unroll 4
        for (int kk = 0; kk < KC; kk++) {
            float4 a4 = *(const float4*)&s_a[kk][tm * 4];
            float4 h0 = ((const float4*)s_h[kk])[lane];
            float4 h1 = ((const float4*)s_h[kk])[32 + lane];
            float am[4] = {a4.x, a4.y, a4.z, a4.w};
            float hq[8] = {h0.x, h0.y, h0.z, h0.w, h1.x, h1.y, h1.z, h1.w};
#pragma unroll
            for (int i = 0; i < 4; i++)
#pragma unroll
                for (int j = 0; j < 8; j++)
                    acc[i][j] = __fmaf_rn(am[i], hq[j], acc[i][j]);
        }
        __syncthreads();
    }

    float4* Cv = (float4*)(Cout + (size_t)b * Nn * Qn);
#pragma unroll
    for (int i = 0; i < 4; i++) {
        int row = m0 + tm * 4 + i;
        float4 o0 = {acc[i][0], acc[i][1], acc[i][2], acc[i][3]};
        float4 o1 = {acc[i][4], acc[i][5], acc[i][6], acc[i][7]};
        Cv[(size_t)row * 64 + lane] = o0;
        Cv[(size_t)row * 64 + 32 + lane] = o1;
    }
}

// ---------------------------------------------------------------------------
// Excite epilogue: h2 = h + C / ne[row]  (R8 verbatim)
// ---------------------------------------------------------------------------
__global__ void add_div_kernel(const float* __restrict__ hin,
                               const float* __restrict__ C,
                               const float* __restrict__ ne,
                               float* __restrict__ hout) {
    int b = blockIdx.y;
    size_t idx = (size_t)blockIdx.x * 256 + threadIdx.x;
    size_t o = (size_t)b * Nn * Qn + idx;
    int row = (int)(idx >> 8);
    hout[o] = __fadd_rn(hin[o], __fdiv_rn(C[o], ne[b * Nn + row]));
}

// ---------------------------------------------------------------------------
// Inhibit epilogue — BOTH batches use the VF4-IC2 UNFUSED reduce class
// (LLVM-aarch64 vectorized XLA:CPU reduce, reassoc without contract):
//   partials over q = 8i + 4j + l (VF=4 lanes l, interleave j=0..1),
//   separate __fmul_rn/__fadd_rn combiners,
//   combine v = v0 + v1 lanewise, then faddp pair tree ((l0+l1)+(l2+l3)).
// One thread per row.
// ---------------------------------------------------------------------------
__device__ __forceinline__ float comb_vf4ic2(const float a[2][4]) {
    float w0 = __fadd_rn(a[0][0], a[1][0]);
    float w1 = __fadd_rn(a[0][1], a[1][1]);
    float w2 = __fadd_rn(a[0][2], a[1][2]);
    float w3 = __fadd_rn(a[0][3], a[1][3]);
    return __fadd_rn(__fadd_rn(w0, w1), __fadd_rn(w2, w3));
}

__global__ void __launch_bounds__(256)
proj_vec(const float* __restrict__ h2, const float* __restrict__ C,
         const float* __restrict__ ni, float* __restrict__ hout,
         float* __restrict__ outp) {
    int b = blockIdx.y;
    int row = blockIdx.x * 256 + threadIdx.x;
    const float* H  = h2 + ((size_t)b * Nn + row) * Qn;
    const float* Cc = C  + ((size_t)b * Nn + row) * Qn;
    float niv = ni[b * Nn + row];

    float pd[2][4] = {}, pu[2][4] = {};
    for (int i = 0; i < Qn / 8; i++) {
#pragma unroll
        for (int j = 0; j < 2; j++)
#pragma unroll
            for (int l = 0; l < 4; l++) {
                int q = 8 * i + 4 * j + l;
                float h = H[q];
                float ie = __fdiv_rn(Cc[q], niv);
                pd[j][l] = __fadd_rn(pd[j][l], __fmul_rn(h, ie));
                pu[j][l] = __fadd_rn(pu[j][l], __fmul_rn(ie, ie));
            }
    }
    float dot = comb_vf4ic2(pd);
    float un  = comb_vf4ic2(pu);
    float coef = __fdiv_rn(dot, __fadd_rn(un, 1e-12f));

    float ps[2][4] = {};
    for (int i = 0; i < Qn / 8; i++) {
#pragma unroll
        for (int j = 0; j < 2; j++)
#pragma unroll
            for (int l = 0; l < 4; l++) {
                int q = 8 * i + 4 * j + l;
                float h = H[q];
                float ie = __fdiv_rn(Cc[q], niv);
                float r = fmaxf(__fsub_rn(h, __fmul_rn(coef, ie)), 0.f);
                ps[j][l] = __fadd_rn(ps[j][l], __fmul_rn(r, r));
            }
    }
    float ss = comb_vf4ic2(ps);
    float nrm = fmaxf(__fsqrt_rn(ss), 1e-8f);

    float* ho = hout + ((size_t)b * Nn + row) * Qn;
    float* oo = outp + ((size_t)b * Nn + row) * Qn;
    for (int q = 0; q < Qn; q++) {
        float h = H[q];
        float ie = __fdiv_rn(Cc[q], niv);
        float r = fmaxf(__fsub_rn(h, __fmul_rn(coef, ie)), 0.f);
        float v = __fdiv_rn(r, nrm);
        ho[q] = v;
        oo[q] = v;
    }
}

// ---------------------------------------------------------------------------
extern "C" void kernel_launch(void* const* d_in, const int* in_sizes, int n_in,
                              void* d_out, int out_size) {
    const float* h0  = nullptr;
    const float* adj = nullptr;
    const float* act = nullptr;
    for (int i = 0; i < n_in; i++) {
        if (in_sizes[i] == Bn * Nn * Qn)      h0  = (const float*)d_in[i];
        else if (in_sizes[i] == Bn * Nn * Nn) adj = (const float*)d_in[i];
        else if (in_sizes[i] == Bn * Nn)      act = (const float*)d_in[i];
    }
    float* out = (float*)d_out;

    float *ph, *ph2, *pC, *pne, *pni, *pne1, *pni1;
    cudaGetSymbolAddress((void**)&ph,   g_h);
    cudaGetSymbolAddress((void**)&ph2,  g_h2);
    cudaGetSymbolAddress((void**)&pC,   g_C);
    cudaGetSymbolAddress((void**)&pne,  g_ne);
    cudaGetSymbolAddress((void**)&pni,  g_ni);
    cudaGetSymbolAddress((void**)&pne1, g_ne1);
    cudaGetSymbolAddress((void**)&pni1, g_ni1);

    dim3 csgrid(Nn / 256, Bn);
    colsum_kernel<false><<<csgrid, 256>>>(adj, nullptr, pne,  pni);
    colsum_kernel<true ><<<csgrid, 256>>>(adj, act,     pne1, pni1);

    dim3 ggrid(Nn / 32, Bn);
    dim3 egrid(Nn * Qn / 256, Bn);
    dim3 pgrid(Nn / 256, Bn);

    const float* hcur = h0;
    for (int it = 0; it < NITERS; ++it) {
        float* out_it = out + (size_t)it * Bn * Nn * Qn;
        if (it == 0) {
            gemm_serial<0, true><<<ggrid, 256>>>(adj, act, hcur, pC);
            add_div_kernel<<<egrid, 256>>>(hcur, pC, pne1, ph2);
            gemm_serial<1, true><<<ggrid, 256>>>(adj, act, ph2, pC);
            proj_vec<<<pgrid, 256>>>(ph2, pC, pni1, ph, out_it);
        } else {
            gemm_serial<0, false><<<ggrid, 256>>>(adj, nullptr, ph, pC);
            add_div_kernel<<<egrid, 256>>>(ph, pC, pne, ph2);
            gemm_serial<1, false><<<ggrid, 256>>>(adj, nullptr, ph2, pC);
            proj_vec<<<pgrid, 256>>>(ph2, pC, pni, ph, out_it);
        }
        hcur = ph;
    }
}

// round 16
// speedup vs baseline: 2.1431x; 2.1431x over previous
#include <cuda_runtime.h>
#include <math.h>
#include <stdint.h>

#define Bn 2
#define Nn 2048
#define Qn 256
#define NITERS 15

// Scratch (device globals)
__device__ __align__(16) float g_h [Bn * Nn * Qn];
__device__ __align__(16) float g_h2[Bn * Nn * Qn];
__device__ __align__(16) float g_C [Bn * Nn * Qn];
__device__ float g_ne [Bn * Nn];
__device__ float g_ni [Bn * Nn];
__device__ float g_ne1[Bn * Nn];
__device__ float g_ni1[Bn * Nn];

// ---------------------------------------------------------------------------
// Column sums: serial ascending n, rn ops, separate mul/add (R15 verbatim,
// plus unroll for MLP)
// ---------------------------------------------------------------------------
template <bool ACT>
__global__ void colsum_kernel(const float* __restrict__ adj,
                              const float* __restrict__ act,
                              float* __restrict__ ne, float* __restrict__ ni) {
    int b = blockIdx.y;
    int m = blockIdx.x * 256 + threadIdx.x;
    const float* A = adj + (size_t)b * Nn * Nn + m;
    float se = 0.f, si = 0.f;
#pragma unroll 4
    for (int n = 0; n < Nn; n++) {
        float v = A[(size_t)n * Nn];
        float e = (v > 0.5f) ? v : 0.f;
        float w = __fsub_rn(1.0f, v);
        float ii = (w > 0.5f) ? w : 0.f;
        if (ACT) {
            float a = act[b * Nn + n];
            e = __fmul_rn(e, a);
            ii = __fmul_rn(ii, a);
        }
        se = __fadd_rn(se, e);
        si = __fadd_rn(si, ii);
    }
    ne[b * Nn + m] = fmaxf(se, 1.f);
    ni[b * Nn + m] = fmaxf(si, 1.f);
}

// ---------------------------------------------------------------------------
// GEMM: per-element strict serial ascending __fmaf_rn chain (bit-identical
// to R15). Tile Mt=32 x Qt=128, 256 thr, 4x4 microtile, double-buffered
// smem (KC=32), grid 64 x 2(Qsplit) x 2(batch) = 256 CTAs.
// MODE 0 (excite): fused epilogue writes h2 = h + acc/ne  (== add_div ops)
// MODE 1 (inhibit): writes C for the proj kernel.
// ---------------------------------------------------------------------------
template <int MODE, bool ACT>
__global__ void __launch_bounds__(256)
gemm_fused(const float* __restrict__ adj, const float* __restrict__ act,
           const float* __restrict__ hin, const float* __restrict__ narr,
           float* __restrict__ outbuf) {
    __shared__ float               s_a[2][32][32];   // 8 KB
    __shared__ __align__(16) float4 s_h[2][32][32];  // 32 KB

    int b   = blockIdx.z;
    int m0  = blockIdx.x * 32;
    int q40 = blockIdx.y * 32;                 // float4 column offset
    int tid = threadIdx.x, lane = tid & 31, tm = tid >> 5;

    const float*  Ab = adj + (size_t)b * Nn * Nn;
    const float4* Hv = (const float4*)(hin + (size_t)b * Nn * Qn);
    const float*  av = ACT ? (act + b * Nn) : nullptr;

    float acc[4][4];
#pragma unroll
    for (int i = 0; i < 4; i++)
#pragma unroll
        for (int j = 0; j < 4; j++) acc[i][j] = 0.f;

    float  pa[4];
    float4 ph[4];

    // --- prologue: load chunk 0 into regs, store to buffer 0 ---
#pragma unroll
    for (int i = 0; i < 4; i++) {
        int idx = tid + i * 256;
        int kk = idx >> 5, mm = idx & 31;
        float v = Ab[(size_t)kk * Nn + m0 + mm];
        float t;
        if (MODE == 0) t = (v > 0.5f) ? v : 0.f;
        else { float w = __fsub_rn(1.f, v); t = (w > 0.5f) ? w : 0.f; }
        if (ACT) t = __fmul_rn(t, av[kk]);
        pa[i] = t;
        ph[i] = Hv[(size_t)kk * 64 + q40 + (idx & 31)];
    }
#pragma unroll
    for (int i = 0; i < 4; i++) {
        int idx = tid + i * 256;
        s_a[0][idx >> 5][idx & 31] = pa[i];
        s_h[0][idx >> 5][idx & 31] = ph[i];
    }
    __syncthreads();

    const int NC = Nn / 32;
    for (int c = 0; c < NC; c++) {
        int cur = c & 1;
        if (c + 1 < NC) {
            int k0 = (c + 1) * 32;
#pragma unroll
            for (int i = 0; i < 4; i++) {
                int idx = tid + i * 256;
                int kk = idx >> 5, mm = idx & 31;
                float v = Ab[(size_t)(k0 + kk) * Nn + m0 + mm];
                float t;
                if (MODE == 0) t = (v > 0.5f) ? v : 0.f;
                else { float w = __fsub_rn(1.f, v); t = (w > 0.5f) ? w : 0.f; }
                if (ACT) t = __fmul_rn(t, av[k0 + kk]);
                pa[i] = t;
                ph[i] = Hv[(size_t)(k0 + kk) * 64 + q40 + (idx & 31)];
            }
        }
#pragma unroll 4
        for (int kk = 0; kk < 32; kk++) {
            float4 a4 = *(const float4*)&s_a[cur][kk][tm * 4];
            float4 h4 = s_h[cur][kk][lane];
            float am[4] = {a4.x, a4.y, a4.z, a4.w};
            float hq[4] = {h4.x, h4.y, h4.z, h4.w};
#pragma unroll
            for (int i = 0; i < 4; i++)
#pragma unroll
                for (int j = 0; j < 4; j++)
                    acc[i][j] = __fmaf_rn(am[i], hq[j], acc[i][j]);
        }
        if (c + 1 < NC) {
            int nb = 1 - cur;
#pragma unroll
            for (int i = 0; i < 4; i++) {
                int idx = tid + i * 256;
                s_a[nb][idx >> 5][idx & 31] = pa[i];
                s_h[nb][idx >> 5][idx & 31] = ph[i];
            }
        }
        __syncthreads();
    }

    float4* Ov = (float4*)(outbuf + (size_t)b * Nn * Qn);
#pragma unroll
    for (int i = 0; i < 4; i++) {
        int row = m0 + tm * 4 + i;
        if (MODE == 0) {
            // fused add_div: identical ops to R15's add_div_kernel
            float nev = narr[b * Nn + row];
            float4 hvv = Hv[(size_t)row * 64 + q40 + lane];
            float4 o;
            o.x = __fadd_rn(hvv.x, __fdiv_rn(acc[i][0], nev));
            o.y = __fadd_rn(hvv.y, __fdiv_rn(acc[i][1], nev));
            o.z = __fadd_rn(hvv.z, __fdiv_rn(acc[i][2], nev));
            o.w = __fadd_rn(hvv.w, __fdiv_rn(acc[i][3], nev));
            Ov[(size_t)row * 64 + q40 + lane] = o;
        } else {
            float4 o = {acc[i][0], acc[i][1], acc[i][2], acc[i][3]};
            Ov[(size_t)row * 64 + q40 + lane] = o;
        }
    }
}

// ---------------------------------------------------------------------------
// Inhibit epilogue — VF4-IC2 UNFUSED reduce class, bit-identical to R15 but
// with the 8 independent partial chains spread over 8 lanes per row
// (lane sub = 4j + l; chain over i identical). Exact combine tree
// w_l = p[0][l]+p[1][l]; ((w0+w1)+(w2+w3)) reproduced via shuffles.
// One warp handles 4 rows; 256 thr/CTA; grid (Nn/32, Bn).
// ---------------------------------------------------------------------------
__global__ void __launch_bounds__(256)
proj_vec(const float* __restrict__ h2, const float* __restrict__ C,
         const float* __restrict__ ni, float* __restrict__ hout,
         float* __restrict__ outp) {
    const unsigned full = 0xffffffffu;
    int b = blockIdx.y;
    int warpid = threadIdx.x >> 5, lane = threadIdx.x & 31;
    int row = blockIdx.x * 32 + warpid * 4 + (lane >> 3);
    int sub = lane & 7;                       // = 4j + l
    int base = lane & 24;

    const float* H  = h2 + ((size_t)b * Nn + row) * Qn;
    const float* Cc = C  + ((size_t)b * Nn + row) * Qn;
    float niv = ni[b * Nn + row];

    // partial chains (i ascending), separate mul/add — exact R15 order
    float pd = 0.f, pu = 0.f;
#pragma unroll 4
    for (int i = 0; i < 32; i++) {
        int q = 8 * i + sub;
        float h = H[q];
        float ie = __fdiv_rn(Cc[q], niv);
        pd = __fadd_rn(pd, __fmul_rn(h, ie));
        pu = __fadd_rn(pu, __fmul_rn(ie, ie));
    }
    // exact comb_vf4ic2 via shuffles
    float d0 = __shfl_sync(full, pd, base + 0), d1 = __shfl_sync(full, pd, base + 1);
    float d2 = __shfl_sync(full, pd, base + 2), d3 = __shfl_sync(full, pd, base + 3);
    float d4 = __shfl_sync(full, pd, base + 4), d5 = __shfl_sync(full, pd, base + 5);
    float d6 = __shfl_sync(full, pd, base + 6), d7 = __shfl_sync(full, pd, base + 7);
    float w0 = __fadd_rn(d0, d4), w1 = __fadd_rn(d1, d5);
    float w2 = __fadd_rn(d2, d6), w3 = __fadd_rn(d3, d7);
    float dot = __fadd_rn(__fadd_rn(w0, w1), __fadd_rn(w2, w3));

    float u0 = __shfl_sync(full, pu, base + 0), u1 = __shfl_sync(full, pu, base + 1);
    float u2 = __shfl_sync(full, pu, base + 2), u3 = __shfl_sync(full, pu, base + 3);
    float u4 = __shfl_sync(full, pu, base + 4), u5 = __shfl_sync(full, pu, base + 5);
    float u6 = __shfl_sync(full, pu, base + 6), u7 = __shfl_sync(full, pu, base + 7);
    float x0 = __fadd_rn(u0, u4), x1 = __fadd_rn(u1, u5);
    float x2 = __fadd_rn(u2, u6), x3 = __fadd_rn(u3, u7);
    float un = __fadd_rn(__fadd_rn(x0, x1), __fadd_rn(x2, x3));

    float coef = __fdiv_rn(dot, __fadd_rn(un, 1e-12f));

    float ps = 0.f;
#pragma unroll 4
    for (int i = 0; i < 32; i++) {
        int q = 8 * i + sub;
        float h = H[q];
        float ie = __fdiv_rn(Cc[q], niv);
        float r = fmaxf(__fsub_rn(h, __fmul_rn(coef, ie)), 0.f);
        ps = __fadd_rn(ps, __fmul_rn(r, r));
    }
    float s0 = __shfl_sync(full, ps, base + 0), s1 = __shfl_sync(full, ps, base + 1);
    float s2 = __shfl_sync(full, ps, base + 2), s3 = __shfl_sync(full, ps, base + 3);
    float s4 = __shfl_sync(full, ps, base + 4), s5 = __shfl_sync(full, ps, base + 5);
    float s6 = __shfl_sync(full, ps, base + 6), s7 = __shfl_sync(full, ps, base + 7);
    float y0 = __fadd_rn(s0, s4), y1 = __fadd_rn(s1, s5);
    float y2 = __fadd_rn(s2, s6), y3 = __fadd_rn(s3, s7);
    float ss = __fadd_rn(__fadd_rn(y0, y1), __fadd_rn(y2, y3));

    float nrm = fmaxf(__fsqrt_rn(ss), 1e-8f);

    float* ho = hout + ((size_t)b * Nn + row) * Qn;
    float* oo = outp + ((size_t)b * Nn + row) * Qn;
#pragma unroll 4
    for (int i = 0; i < 32; i++) {
        int q = 8 * i + sub;
        float h = H[q];
        float ie = __fdiv_rn(Cc[q], niv);
        float r = fmaxf(__fsub_rn(h, __fmul_rn(coef, ie)), 0.f);
        float v = __fdiv_rn(r, nrm);
        ho[q] = v;
        oo[q] = v;
    }
}

// ---------------------------------------------------------------------------
extern "C" void kernel_launch(void* const* d_in, const int* in_sizes, int n_in,
                              void* d_out, int out_size) {
    const float* h0  = nullptr;
    const float* adj = nullptr;
    const float* act = nullptr;
    for (int i = 0; i < n_in; i++) {
        if (in_sizes[i] == Bn * Nn * Qn)      h0  = (const float*)d_in[i];
        else if (in_sizes[i] == Bn * Nn * Nn) adj = (const float*)d_in[i];
        else if (in_sizes[i] == Bn * Nn)      act = (const float*)d_in[i];
    }
    float* out = (float*)d_out;

    float *ph, *ph2, *pC, *pne, *pni, *pne1, *pni1;
    cudaGetSymbolAddress((void**)&ph,   g_h);
    cudaGetSymbolAddress((void**)&ph2,  g_h2);
    cudaGetSymbolAddress((void**)&pC,   g_C);
    cudaGetSymbolAddress((void**)&pne,  g_ne);
    cudaGetSymbolAddress((void**)&pni,  g_ni);
    cudaGetSymbolAddress((void**)&pne1, g_ne1);
    cudaGetSymbolAddress((void**)&pni1, g_ni1);

    dim3 csgrid(Nn / 256, Bn);
    colsum_kernel<false><<<csgrid, 256>>>(adj, nullptr, pne,  pni);
    colsum_kernel<true ><<<csgrid, 256>>>(adj, act,     pne1, pni1);

    dim3 ggrid(Nn / 32, Qn / 128, Bn);     // 64 x 2 x 2 = 256 CTAs
    dim3 pgrid(Nn / 32, Bn);               // 64 x 2

    const float* hcur = h0;
    for (int it = 0; it < NITERS; ++it) {
        float* out_it = out + (size_t)it * Bn * Nn * Qn;
        if (it == 0) {
            gemm_fused<0, true><<<ggrid, 256>>>(adj, act, hcur, pne1, ph2);
            gemm_fused<1, true><<<ggrid, 256>>>(adj, act, ph2, nullptr, pC);
            proj_vec<<<pgrid, 256>>>(ph2, pC, pni1, ph, out_it);
        } else {
            gemm_fused<0, false><<<ggrid, 256>>>(adj, nullptr, ph, pne, ph2);
            gemm_fused<1, false><<<ggrid, 256>>>(adj, nullptr, ph2, nullptr, pC);
            proj_vec<<<pgrid, 256>>>(ph2, pC, pni, ph, out_it);
        }
        hcur = ph;
    }
}

// round 17
// speedup vs baseline: 2.1795x; 1.0170x over previous
#include <cuda_runtime.h>
#include <math.h>
#include <stdint.h>

#define Bn 2
#define Nn 2048
#define Qn 256
#define NITERS 15

// Scratch (device globals)
__device__ __align__(16) float g_h [Bn * Nn * Qn];
__device__ __align__(16) float g_h2[Bn * Nn * Qn];
__device__ __align__(16) float g_C [Bn * Nn * Qn];
__device__ float g_ne [Bn * Nn];
__device__ float g_ni [Bn * Nn];
__device__ float g_ne1[Bn * Nn];
__device__ float g_ni1[Bn * Nn];

// ---------------------------------------------------------------------------
// Packed f32x2 helpers: two independent IEEE-rn fp32 FMAs per instruction.
// Per-lane arithmetic identical to __fmaf_rn -> chains stay bitwise exact.
// ---------------------------------------------------------------------------
__device__ __forceinline__ unsigned long long pack2(float x, float y) {
    unsigned long long d;
    asm("mov.b64 %0, {%1,%2};" : "=l"(d) : "f"(x), "f"(y));
    return d;
}
__device__ __forceinline__ void unpack2(unsigned long long d, float& x, float& y) {
    asm("mov.b64 {%0,%1}, %2;" : "=f"(x), "=f"(y) : "l"(d));
}
__device__ __forceinline__ unsigned long long fma2(unsigned long long a,
                                                   unsigned long long b,
                                                   unsigned long long c) {
    unsigned long long d;
    asm("fma.rn.f32x2 %0, %1, %2, %3;" : "=l"(d) : "l"(a), "l"(b), "l"(c));
    return d;
}

// ---------------------------------------------------------------------------
// Column sums: serial ascending n, rn ops, separate mul/add (verbatim)
// ---------------------------------------------------------------------------
template <bool ACT>
__global__ void colsum_kernel(const float* __restrict__ adj,
                              const float* __restrict__ act,
                              float* __restrict__ ne, float* __restrict__ ni) {
    int b = blockIdx.y;
    int m = blockIdx.x * 256 + threadIdx.x;
    const float* A = adj + (size_t)b * Nn * Nn + m;
    float se = 0.f, si = 0.f;
#pragma unroll 4
    for (int n = 0; n < Nn; n++) {
        float v = A[(size_t)n * Nn];
        float e = (v > 0.5f) ? v : 0.f;
        float w = __fsub_rn(1.0f, v);
        float ii = (w > 0.5f) ? w : 0.f;
        if (ACT) {
            float a = act[b * Nn + n];
            e = __fmul_rn(e, a);
            ii = __fmul_rn(ii, a);
        }
        se = __fadd_rn(se, e);
        si = __fadd_rn(si, ii);
    }
    ne[b * Nn + m] = fmaxf(se, 1.f);
    ni[b * Nn + m] = fmaxf(si, 1.f);
}

// ---------------------------------------------------------------------------
// GEMM: per-element strict serial ascending rn-FMA chain — now executed
// two chains (adjacent q) per FFMA2 instruction. Bitwise identical results.
// Tile Mt=32 x Qt=128, 256 thr, 4x4 microtile, double-buffered smem,
// grid 64 x 2(Qsplit) x 2(batch) = 256 CTAs.
// MODE 0 (excite): fused epilogue writes h2 = h + acc/ne
// MODE 1 (inhibit): writes C for the proj kernel.
// ---------------------------------------------------------------------------
template <int MODE, bool ACT>
__global__ void __launch_bounds__(256)
gemm_fused(const float* __restrict__ adj, const float* __restrict__ act,
           const float* __restrict__ hin, const float* __restrict__ narr,
           float* __restrict__ outbuf) {
    __shared__ float                s_a[2][32][32];   // 8 KB
    __shared__ __align__(16) float4 s_h[2][32][32];   // 32 KB

    int b   = blockIdx.z;
    int m0  = blockIdx.x * 32;
    int q40 = blockIdx.y * 32;                 // float4 column offset
    int tid = threadIdx.x, lane = tid & 31, tm = tid >> 5;

    const float*  Ab = adj + (size_t)b * Nn * Nn;
    const float4* Hv = (const float4*)(hin + (size_t)b * Nn * Qn);
    const float*  av = ACT ? (act + b * Nn) : nullptr;

    unsigned long long acc2[4][2];
#pragma unroll
    for (int i = 0; i < 4; i++) { acc2[i][0] = 0ull; acc2[i][1] = 0ull; }

    float  pa[4];
    float4 ph[4];

    // --- prologue: load chunk 0 into regs, store to buffer 0 ---
#pragma unroll
    for (int i = 0; i < 4; i++) {
        int idx = tid + i * 256;
        int kk = idx >> 5, mm = idx & 31;
        float v = Ab[(size_t)kk * Nn + m0 + mm];
        float t;
        if (MODE == 0) t = (v > 0.5f) ? v : 0.f;
        else { float w = __fsub_rn(1.f, v); t = (w > 0.5f) ? w : 0.f; }
        if (ACT) t = __fmul_rn(t, av[kk]);
        pa[i] = t;
        ph[i] = Hv[(size_t)kk * 64 + q40 + (idx & 31)];
    }
#pragma unroll
    for (int i = 0; i < 4; i++) {
        int idx = tid + i * 256;
        s_a[0][idx >> 5][idx & 31] = pa[i];
        s_h[0][idx >> 5][idx & 31] = ph[i];
    }
    __syncthreads();

    const int NC = Nn / 32;
    for (int c = 0; c < NC; c++) {
        int cur = c & 1;
        if (c + 1 < NC) {
            int k0 = (c + 1) * 32;
#pragma unroll
            for (int i = 0; i < 4; i++) {
                int idx = tid + i * 256;
                int kk = idx >> 5, mm = idx & 31;
                float v = Ab[(size_t)(k0 + kk) * Nn + m0 + mm];
                float t;
                if (MODE == 0) t = (v > 0.5f) ? v : 0.f;
                else { float w = __fsub_rn(1.f, v); t = (w > 0.5f) ? w : 0.f; }
                if (ACT) t = __fmul_rn(t, av[k0 + kk]);
                pa[i] = t;
                ph[i] = Hv[(size_t)(k0 + kk) * 64 + q40 + (idx & 31)];
            }
        }
#pragma unroll 4
        for (int kk = 0; kk < 32; kk++) {
            float4 a4 = *(const float4*)&s_a[cur][kk][tm * 4];
            ulonglong2 h2 = *(const ulonglong2*)&s_h[cur][kk][lane];
            unsigned long long am2[4];
            am2[0] = pack2(a4.x, a4.x);
            am2[1] = pack2(a4.y, a4.y);
            am2[2] = pack2(a4.z, a4.z);
            am2[3] = pack2(a4.w, a4.w);
#pragma unroll
            for (int i = 0; i < 4; i++) {
                acc2[i][0] = fma2(am2[i], h2.x, acc2[i][0]);
                acc2[i][1] = fma2(am2[i], h2.y, acc2[i][1]);
            }
        }
        if (c + 1 < NC) {
            int nb = 1 - cur;
#pragma unroll
            for (int i = 0; i < 4; i++) {
                int idx = tid + i * 256;
                s_a[nb][idx >> 5][idx & 31] = pa[i];
                s_h[nb][idx >> 5][idx & 31] = ph[i];
            }
        }
        __syncthreads();
    }

    float4* Ov = (float4*)(outbuf + (size_t)b * Nn * Qn);
#pragma unroll
    for (int i = 0; i < 4; i++) {
        int row = m0 + tm * 4 + i;
        float a0, a1, a2, a3;
        unpack2(acc2[i][0], a0, a1);
        unpack2(acc2[i][1], a2, a3);
        if (MODE == 0) {
            float nev = narr[b * Nn + row];
            float4 hvv = Hv[(size_t)row * 64 + q40 + lane];
            float4 o;
            o.x = __fadd_rn(hvv.x, __fdiv_rn(a0, nev));
            o.y = __fadd_rn(hvv.y, __fdiv_rn(a1, nev));
            o.z = __fadd_rn(hvv.z, __fdiv_rn(a2, nev));
            o.w = __fadd_rn(hvv.w, __fdiv_rn(a3, nev));
            Ov[(size_t)row * 64 + q40 + lane] = o;
        } else {
            float4 o = {a0, a1, a2, a3};
            Ov[(size_t)row * 64 + q40 + lane] = o;
        }
    }
}

// ---------------------------------------------------------------------------
// Inhibit epilogue — VF4-IC2 UNFUSED reduce class (R16 verbatim):
// 8 partial chains over 8 lanes/row, exact faddp combine via shuffles.
// ---------------------------------------------------------------------------
__global__ void __launch_bounds__(256)
proj_vec(const float* __restrict__ h2, const float* __restrict__ C,
         const float* __restrict__ ni, float* __restrict__ hout,
         float* __restrict__ outp) {
    const unsigned full = 0xffffffffu;
    int b = blockIdx.y;
    int warpid = threadIdx.x >> 5, lane = threadIdx.x & 31;
    int row = blockIdx.x * 32 + warpid * 4 + (lane >> 3);
    int sub = lane & 7;
    int base = lane & 24;

    const float* H  = h2 + ((size_t)b * Nn + row) * Qn;
    const float* Cc = C  + ((size_t)b * Nn + row) * Qn;
    float niv = ni[b * Nn + row];

    float pd = 0.f, pu = 0.f;
#pragma unroll 4
    for (int i = 0; i < 32; i++) {
        int q = 8 * i + sub;
        float h = H[q];
        float ie = __fdiv_rn(Cc[q], niv);
        pd = __fadd_rn(pd, __fmul_rn(h, ie));
        pu = __fadd_rn(pu, __fmul_rn(ie, ie));
    }
    float d0 = __shfl_sync(full, pd, base + 0), d1 = __shfl_sync(full, pd, base + 1);
    float d2 = __shfl_sync(full, pd, base + 2), d3 = __shfl_sync(full, pd, base + 3);
    float d4 = __shfl_sync(full, pd, base + 4), d5 = __shfl_sync(full, pd, base + 5);
    float d6 = __shfl_sync(full, pd, base + 6), d7 = __shfl_sync(full, pd, base + 7);
    float w0 = __fadd_rn(d0, d4), w1 = __fadd_rn(d1, d5);
    float w2 = __fadd_rn(d2, d6), w3 = __fadd_rn(d3, d7);
    float dot = __fadd_rn(__fadd_rn(w0, w1), __fadd_rn(w2, w3));

    float u0 = __shfl_sync(full, pu, base + 0), u1 = __shfl_sync(full, pu, base + 1);
    float u2 = __shfl_sync(full, pu, base + 2), u3 = __shfl_sync(full, pu, base + 3);
    float u4 = __shfl_sync(full, pu, base + 4), u5 = __shfl_sync(full, pu, base + 5);
    float u6 = __shfl_sync(full, pu, base + 6), u7 = __shfl_sync(full, pu, base + 7);
    float x0 = __fadd_rn(u0, u4), x1 = __fadd_rn(u1, u5);
    float x2 = __fadd_rn(u2, u6), x3 = __fadd_rn(u3, u7);
    float un = __fadd_rn(__fadd_rn(x0, x1), __fadd_rn(x2, x3));

    float coef = __fdiv_rn(dot, __fadd_rn(un, 1e-12f));

    float ps = 0.f;
#pragma unroll 4
    for (int i = 0; i < 32; i++) {
        int q = 8 * i + sub;
        float h = H[q];
        float ie = __fdiv_rn(Cc[q], niv);
        float r = fmaxf(__fsub_rn(h, __fmul_rn(coef, ie)), 0.f);
        ps = __fadd_rn(ps, __fmul_rn(r, r));
    }
    float s0 = __shfl_sync(full, ps, base + 0), s1 = __shfl_sync(full, ps, base + 1);
    float s2 = __shfl_sync(full, ps, base + 2), s3 = __shfl_sync(full, ps, base + 3);
    float s4 = __shfl_sync(full, ps, base + 4), s5 = __shfl_sync(full, ps, base + 5);
    float s6 = __shfl_sync(full, ps, base + 6), s7 = __shfl_sync(full, ps, base + 7);
    float y0 = __fadd_rn(s0, s4), y1 = __fadd_rn(s1, s5);
    float y2 = __fadd_rn(s2, s6), y3 = __fadd_rn(s3, s7);
    float ss = __fadd_rn(__fadd_rn(y0, y1), __fadd_rn(y2, y3));

    float nrm = fmaxf(__fsqrt_rn(ss), 1e-8f);

    float* ho = hout + ((size_t)b * Nn + row) * Qn;
    float* oo = outp + ((size_t)b * Nn + row) * Qn;
#pragma unroll 4
    for (int i = 0; i < 32; i++) {
        int q = 8 * i + sub;
        float h = H[q];
        float ie = __fdiv_rn(Cc[q], niv);
        float r = fmaxf(__fsub_rn(h, __fmul_rn(coef, ie)), 0.f);
        float v = __fdiv_rn(r, nrm);
        ho[q] = v;
        oo[q] = v;
    }
}

// ---------------------------------------------------------------------------
extern "C" void kernel_launch(void* const* d_in, const int* in_sizes, int n_in,
                              void* d_out, int out_size) {
    const float* h0  = nullptr;
    const float* adj = nullptr;
    const float* act = nullptr;
    for (int i = 0; i < n_in; i++) {
        if (in_sizes[i] == Bn * Nn * Qn)      h0  = (const float*)d_in[i];
        else if (in_sizes[i] == Bn * Nn * Nn) adj = (const float*)d_in[i];
        else if (in_sizes[i] == Bn * Nn)      act = (const float*)d_in[i];
    }
    float* out = (float*)d_out;

    float *ph, *ph2, *pC, *pne, *pni, *pne1, *pni1;
    cudaGetSymbolAddress((void**)&ph,   g_h);
    cudaGetSymbolAddress((void**)&ph2,  g_h2);
    cudaGetSymbolAddress((void**)&pC,   g_C);
    cudaGetSymbolAddress((void**)&pne,  g_ne);
    cudaGetSymbolAddress((void**)&pni,  g_ni);
    cudaGetSymbolAddress((void**)&pne1, g_ne1);
    cudaGetSymbolAddress((void**)&pni1, g_ni1);

    dim3 csgrid(Nn / 256, Bn);
    colsum_kernel<false><<<csgrid, 256>>>(adj, nullptr, pne,  pni);
    colsum_kernel<true ><<<csgrid, 256>>>(adj, act,     pne1, pni1);

    dim3 ggrid(Nn / 32, Qn / 128, Bn);     // 64 x 2 x 2 = 256 CTAs
    dim3 pgrid(Nn / 32, Bn);               // 64 x 2

    const float* hcur = h0;
    for (int it = 0; it < NITERS; ++it) {
        float* out_it = out + (size_t)it * Bn * Nn * Qn;
        if (it == 0) {
            gemm_fused<0, true><<<ggrid, 256>>>(adj, act, hcur, pne1, ph2);
            gemm_fused<1, true><<<ggrid, 256>>>(adj, act, ph2, nullptr, pC);
            proj_vec<<<pgrid, 256>>>(ph2, pC, pni1, ph, out_it);
        } else {
            gemm_fused<0, false><<<ggrid, 256>>>(adj, nullptr, ph, pne, ph2);
            gemm_fused<1, false><<<ggrid, 256>>>(adj, nullptr, ph2, nullptr, pC);
            proj_vec<<<pgrid, 256>>>(ph2, pC, pni, ph, out_it);
        }
        hcur = ph;
    }
}